// round 10
// baseline (speedup 1.0000x reference)
#include <cuda_runtime.h>
#include <cuda_bf16.h>
#include <cuda_fp16.h>
#include <cstdint>

#define Bsz 16
#define Cch 256
#define Hh 48
#define Ww 160
#define HW (Hh*Ww)          // 7680
#define MM 256
#define KK 256

// Scratch (device globals)
__device__ __half g_Wh[MM * KK];                      // fp16 weights
__device__ float  g_part[32 * Bsz * HW];              // conv partials
__device__ float4 g_px[Bsz * HW];                     // per-pixel (iy0, wy, dsamp, _)

// ---------------------------------------------------------------------------
// helpers
// ---------------------------------------------------------------------------
__device__ __forceinline__ uint32_t s2u(const void* p) {
    uint32_t a;
    asm("{ .reg .u64 t; cvta.to.shared.u64 t, %1; cvt.u32.u64 %0, t; }" : "=r"(a) : "l"(p));
    return a;
}
__device__ __forceinline__ void ldmatrix_x4(uint32_t& r0, uint32_t& r1, uint32_t& r2, uint32_t& r3, uint32_t a) {
    asm volatile("ldmatrix.sync.aligned.m8n8.x4.shared.b16 {%0,%1,%2,%3}, [%4];"
                 : "=r"(r0), "=r"(r1), "=r"(r2), "=r"(r3) : "r"(a));
}
__device__ __forceinline__ void ldmatrix_x2_trans(uint32_t& r0, uint32_t& r1, uint32_t a) {
    asm volatile("ldmatrix.sync.aligned.m8n8.x2.trans.shared.b16 {%0,%1}, [%2];"
                 : "=r"(r0), "=r"(r1) : "r"(a));
}
__device__ __forceinline__ void mma_f16(float* c, const uint32_t* a, const uint32_t* b) {
    asm volatile("mma.sync.aligned.m16n8k16.row.col.f32.f16.f16.f32 "
                 "{%0,%1,%2,%3}, {%4,%5,%6,%7}, {%8,%9}, {%0,%1,%2,%3};"
                 : "+f"(c[0]), "+f"(c[1]), "+f"(c[2]), "+f"(c[3])
                 : "r"(a[0]), "r"(a[1]), "r"(a[2]), "r"(a[3]), "r"(b[0]), "r"(b[1]));
}
__device__ __forceinline__ void cpasync16(uint32_t dst, const void* src) {
    asm volatile("cp.async.cg.shared.global [%0], [%1], 16;" :: "r"(dst), "l"(src) : "memory");
}
#define CP_COMMIT() asm volatile("cp.async.commit_group;" ::: "memory")
#define CP_WAIT2()  asm volatile("cp.async.wait_group 2;" ::: "memory")

// smem layout (bytes):
//   A stages: 4 x (256 rows x 64B data, 80B pitch) = 4 x 20480
//   B resident: 256 rows x 256B data, 272B pitch   = 69632
#define ASTG   20480
#define OFF_B  81920
#define OFF_DS 151552
#define OFF_WE (OFF_DS + 512)
#define OFF_BE (OFF_WE + 1024)
#define SMEM_TOTAL (OFF_BE + 1024)

// ---------------------------------------------------------------------------
// Kernel 0: w_ext[:,1:] -> fp16
// ---------------------------------------------------------------------------
__global__ void prepA_kernel(const float* __restrict__ w_ext) {
    int i = blockIdx.x * blockDim.x + threadIdx.x;
    if (i < MM * KK) {
        int m = i >> 8, c = i & 255;
        g_Wh[i] = __float2half(w_ext[m * 257 + 1 + c]);
    }
}

// ---------------------------------------------------------------------------
// Kernel 1a: conv partials — one block per (8 rows, 8-channel chunk, batch)
// ---------------------------------------------------------------------------
__global__ void __launch_bounds__(160)
conv_part_kernel(const float* __restrict__ feats, const float* __restrict__ w_disp) {
    const int y0 = blockIdx.x * 8;
    const int cchunk = blockIdx.y;
    const int b = blockIdx.z;
    const int wx = threadIdx.x;

    __shared__ float sw[72];
    __shared__ float srow[10][Ww];
    if (wx < 72) sw[wx] = w_disp[cchunk * 72 + wx];

    float acc[8];
#pragma unroll
    for (int i = 0; i < 8; ++i) acc[i] = 0.f;
    const float* Fb = feats + ((size_t)b * Cch + cchunk * 8) * HW;
    __syncthreads();

    for (int cc = 0; cc < 8; ++cc) {
        const float* Fc = Fb + (size_t)cc * HW;
#pragma unroll
        for (int r = 0; r < 10; ++r) {
            int yy = y0 - 1 + r;
            srow[r][wx] = (yy >= 0 && yy < Hh) ? Fc[yy * Ww + wx] : 0.f;
        }
        __syncthreads();
        float v[10][3];
#pragma unroll
        for (int r = 0; r < 10; ++r) {
            v[r][0] = (wx > 0)      ? srow[r][wx - 1] : 0.f;
            v[r][1] =                 srow[r][wx];
            v[r][2] = (wx < Ww - 1) ? srow[r][wx + 1] : 0.f;
        }
        const float* wc = &sw[cc * 9];
#pragma unroll
        for (int ky = 0; ky < 3; ++ky)
#pragma unroll
            for (int kx = 0; kx < 3; ++kx) {
                float wv = wc[ky * 3 + kx];
#pragma unroll
                for (int ry = 0; ry < 8; ++ry)
                    acc[ry] = fmaf(v[ry + ky][kx], wv, acc[ry]);
            }
        __syncthreads();
    }
    float* P = g_part + (size_t)cchunk * (Bsz * HW) + ((size_t)b * Hh + y0) * Ww + wx;
#pragma unroll
    for (int ry = 0; ry < 8; ++ry) P[ry * Ww] = acc[ry];
}

// ---------------------------------------------------------------------------
// Kernel 1b: reduce partials + scalar math -> g_px
// ---------------------------------------------------------------------------
__global__ void px_kernel(const float* __restrict__ P2, const float* __restrict__ b_disp) {
    int idx = blockIdx.x * 256 + threadIdx.x;
    int b = idx / HW;
    int rem = idx - b * HW;
    int y = rem / Ww;

    float a = 0.f;
#pragma unroll
    for (int j = 0; j < 32; ++j) a += g_part[(size_t)j * (Bsz * HW) + idx];

    const float fy = P2[b * 12 + 5] * 0.0625f;
    const float cy = P2[b * 12 + 6] * 0.0625f;
    const float Ty = P2[b * 12 + 7] * 0.0625f;
    const float denomD = fabsf(fy * 1.65f + Ty) + 1e-10f;
    const float ysb_den = 2.f * (1.65f - 0.5f * 1.535f);

    float d = tanhf(a + b_disp[0]);
    float disp = 0.1f * d;
    float ybase = -1.f + 2.f * (float)y / 47.f;
    float ysb = fmaxf(1.535f * ((float)y - cy) / ysb_den, 0.f) * (1.f / 24.f);
    float gy = ybase + ysb + disp;
    float iy = fminf(fmaxf((gy + 1.f) * 23.5f, 0.f), 47.f);
    float iy0f = floorf(iy);
    float wy = iy - iy0f;
    int iy0 = (int)iy0f;
    int iy1 = min(iy0 + 1, Hh - 1);
    float d0 = fmaxf(fy * 0.54f * ((float)iy0 - cy) / denomD, 0.f);
    float d1 = fmaxf(fy * 0.54f * ((float)iy1 - cy) / denomD, 0.f);
    float ds = (1.f - wy) * d0 + wy * d1;
    g_px[idx] = make_float4(iy0f, wy, ds, 0.f);
}

// ---------------------------------------------------------------------------
// Kernel 2: fused gather + fp16 GEMM + epilogue.
// B tile (256 ch x 128 px fp16) gathered+blended into resident smem once;
// A (weights) streamed via 4-stage cp.async; 8 warps, warp tile 64x64.
// grid = (60, 1, 16), block = 256.
// ---------------------------------------------------------------------------
__global__ void __launch_bounds__(256)
gemm_fused(const float* __restrict__ feats,
           const float* __restrict__ w_ext,
           const float* __restrict__ b_ext,
           const float* __restrict__ alpha,
           float* __restrict__ out) {
    extern __shared__ char sm[];
    const uint32_t smb = s2u(sm);
    const int tid  = threadIdx.x;
    const int wid  = tid >> 5, lane = tid & 31;
    const int b    = blockIdx.z;
    const int n0   = blockIdx.x * 128;

    float* s_ds = (float*)(sm + OFF_DS);
    float* s_we = (float*)(sm + OFF_WE);
    float* s_be = (float*)(sm + OFF_BE);

    if (tid < 128) s_ds[tid] = g_px[(size_t)b * HW + n0 + tid].z;
    s_we[tid] = w_ext[tid * 257];
    s_be[tid] = b_ext[tid];

    // A-stream producer: 4 x 16B chunks per thread per stage (BK=32)
    auto issue = [&](int ks) {
        const uint32_t base = smb + (ks & 3) * ASTG;
#pragma unroll
        for (int i = 0; i < 4; ++i) {
            int c = tid + i * 256;
            int row = c >> 2, seg = c & 3;
            cpasync16(base + row * 80 + seg * 16,
                      (const char*)g_Wh + row * 512 + ks * 64 + seg * 16);
        }
    };

    issue(0); CP_COMMIT();
    issue(1); CP_COMMIT();
    issue(2); CP_COMMIT();

    // ---- B gather: blend two feature rows per pixel, pack px pairs ----
    {
        const int tp = tid & 63;             // pixel-pair index
        const int cstart = tid >> 6;         // 0..3
        const int pxa = n0 + 2 * tp;
        float4 pA = g_px[(size_t)b * HW + pxa];
        float4 pB = g_px[(size_t)b * HW + pxa + 1];
        int iy0a = (int)pA.x, iy0b = (int)pB.x;
        int wa = pxa % Ww, wb = (pxa + 1) % Ww;
        const int o0a = iy0a * Ww + wa, o1a = min(iy0a + 1, Hh - 1) * Ww + wa;
        const int o0b = iy0b * Ww + wb, o1b = min(iy0b + 1, Hh - 1) * Ww + wb;
        const float wya = pA.y, wyb = pB.y;
        const float* F = feats + (size_t)b * Cch * HW;
#pragma unroll 4
        for (int i = 0; i < 64; ++i) {
            const int c = cstart + 4 * i;
            const float* Fc = F + (size_t)c * HW;
            float f00 = __ldg(Fc + o0a), f01 = __ldg(Fc + o1a);
            float f10 = __ldg(Fc + o0b), f11 = __ldg(Fc + o1b);
            float v0 = fmaf(wya, f01 - f00, f00);
            float v1 = fmaf(wyb, f11 - f10, f10);
            __half2 h = __floats2half2_rn(v0, v1);
            *(__half2*)(sm + OFF_B + c * 272 + tp * 4) = h;
        }
    }

    // consumer mapping
    const int cb = (wid >> 1) * 64;       // channel base
    const int pb = (wid & 1) * 64;        // pixel base
    const uint32_t aOff = (cb + (lane & 15)) * 80 + ((lane >> 4) * 16);
    const uint32_t bOff = smb + OFF_B + (lane & 15) * 272 + pb * 2;

    float acc[4][8][4];
#pragma unroll
    for (int i = 0; i < 4; ++i)
#pragma unroll
        for (int j = 0; j < 8; ++j)
#pragma unroll
            for (int q = 0; q < 4; ++q) acc[i][j][q] = 0.f;

    for (int ks = 0; ks < 8; ++ks) {
        CP_WAIT2();
        __syncthreads();
        const uint32_t aStage = smb + (ks & 3) * ASTG;
#pragma unroll
        for (int ksub = 0; ksub < 2; ++ksub) {
            const uint32_t aBase = aStage + aOff + ksub * 32;
            const uint32_t bBase = bOff + (ks * 32 + ksub * 16) * 272;
            uint32_t aF[4][4], bF[8][2];
#pragma unroll
            for (int mt = 0; mt < 4; ++mt)
                ldmatrix_x4(aF[mt][0], aF[mt][1], aF[mt][2], aF[mt][3], aBase + mt * 16 * 80);
#pragma unroll
            for (int nt = 0; nt < 8; ++nt)
                ldmatrix_x2_trans(bF[nt][0], bF[nt][1], bBase + nt * 16);
#pragma unroll
            for (int mt = 0; mt < 4; ++mt)
#pragma unroll
                for (int nt = 0; nt < 8; ++nt) mma_f16(acc[mt][nt], aF[mt], bF[nt]);
        }
        if (ks + 3 < 8) issue(ks + 3);
        CP_COMMIT();
    }

    // ---- epilogue: D[chan][px] ----
    const float al = alpha[0];
    const float* Fb = feats + (size_t)b * Cch * HW;
    float* Ob = out + (size_t)b * Cch * HW + n0;
    const float* Fr = Fb + n0;
    const int rr = lane >> 2;
    const int ccol = (lane & 3) * 2;

#pragma unroll
    for (int mt = 0; mt < 4; ++mt) {
#pragma unroll
        for (int nt = 0; nt < 8; ++nt) {
            const int pxl = pb + nt * 8 + ccol;
            const float ds0 = s_ds[pxl], ds1 = s_ds[pxl + 1];
#pragma unroll
            for (int h = 0; h < 2; ++h) {
                const int ch = cb + mt * 16 + rr + h * 8;
                const float we = s_we[ch], be = s_be[ch];
                float v0 = acc[mt][nt][2 * h + 0] + fmaf(we, ds0, be);
                float v1 = acc[mt][nt][2 * h + 1] + fmaf(we, ds1, be);
                const float2 x = __ldg((const float2*)(Fr + (size_t)ch * HW + pxl));
                float2 r;
                r.x = fmaxf(fmaf(v0, al, x.x), 0.f);
                r.y = fmaxf(fmaf(v1, al, x.y), 0.f);
                *(float2*)(Ob + (size_t)ch * HW + pxl) = r;
            }
        }
    }
}

// ---------------------------------------------------------------------------
extern "C" void kernel_launch(void* const* d_in, const int* in_sizes, int n_in,
                              void* d_out, int out_size) {
    const float* feats  = (const float*)d_in[0];
    const float* P2     = (const float*)d_in[1];
    const float* w_disp = (const float*)d_in[2];
    const float* b_disp = (const float*)d_in[3];
    const float* w_ext  = (const float*)d_in[4];
    const float* b_ext  = (const float*)d_in[5];
    const float* alpha  = (const float*)d_in[6];
    float* out = (float*)d_out;

    cudaFuncSetAttribute(gemm_fused, cudaFuncAttributeMaxDynamicSharedMemorySize, SMEM_TOTAL);

    prepA_kernel<<<256, 256>>>(w_ext);
    conv_part_kernel<<<dim3(6, 32, Bsz), 160>>>(feats, w_disp);
    px_kernel<<<Bsz * HW / 256, 256>>>(P2, b_disp);
    gemm_fused<<<dim3(HW / 128, 1, Bsz), 256, SMEM_TOTAL>>>(feats, w_ext, b_ext, alpha, out);
}